// round 14
// baseline (speedup 1.0000x reference)
#include <cuda_runtime.h>

// out[b,e,t] = v2[t]*x[b,e,t] + bias[t] + P[t]
// P[t] = sum_{s<t} x[b,e,s]*w[s]*d^(t-s),  d = clip(decay[1], 0.9, 1.0)
//
// Decayed prefix scan along S; all scan multipliers are data-independent
// powers of d. Software-pipelined: row r+1's A-chain + warp shuffle-scan
// (registers/shuffles only) executes in the shadow of row r's post-barrier
// carry + epilogue + store — the two streams are independent ILP in the same
// thread, so the shuffle-scan latency is no longer on the critical path.

#define SEQ 2048
#define CHUNK 8
#define THREADS 256          // 256 * 8 = 2048 = SEQ
#define NWARP (THREADS / 32)
#define RPB 8                // rows per block

__device__ __forceinline__ float chain_scan(const float* __restrict__ xv,
                                            const float* __restrict__ wv,
                                            float d, float m1, float m2,
                                            float m4, float m8, float m16,
                                            int lane)
{
    // A = sum_j x[j]*w[j]*d^(CHUNK-j), then Kogge-Stone inclusive scan with
    // precomputed uniform multipliers (powers of d).
    float A = 0.f;
#pragma unroll
    for (int j = 0; j < CHUNK; j++) A = d * fmaf(xv[j], wv[j], A);
    float ap;
    ap = __shfl_up_sync(0xffffffffu, A, 1);  if (lane >= 1)  A = fmaf(m1,  ap, A);
    ap = __shfl_up_sync(0xffffffffu, A, 2);  if (lane >= 2)  A = fmaf(m2,  ap, A);
    ap = __shfl_up_sync(0xffffffffu, A, 4);  if (lane >= 4)  A = fmaf(m4,  ap, A);
    ap = __shfl_up_sync(0xffffffffu, A, 8);  if (lane >= 8)  A = fmaf(m8,  ap, A);
    ap = __shfl_up_sync(0xffffffffu, A, 16); if (lane >= 16) A = fmaf(m16, ap, A);
    return A;
}

__global__ void __launch_bounds__(THREADS, 4)
decay_scan_kernel(const float* __restrict__ x,
                  const float* __restrict__ w,
                  const float* __restrict__ v2,
                  const float* __restrict__ bias,
                  const float* __restrict__ decay,
                  float* __restrict__ out,
                  int rows)
{
    const int tid   = threadIdx.x;
    const int lane  = tid & 31;
    const int warp  = tid >> 5;
    const int sbase = tid * CHUNK;

    const float d = fminf(fmaxf(decay[1], 0.9f), 1.0f);

    // uniform decay powers
    float d8 = d * d; d8 = d8 * d8; d8 = d8 * d8;   // d^8
    const float m1  = d8;
    const float m2  = m1 * m1;
    const float m4  = m2 * m2;
    const float m8  = m4 * m4;
    const float m16 = m8 * m8;
    const float d256 = m16 * m16;
    const float Me = exp2f(8.0f * (float)lane * __log2f(d));  // d^(8*lane)

    // register-cached params
    const float4 w0  = *reinterpret_cast<const float4*>(w    + sbase);
    const float4 w1  = *reinterpret_cast<const float4*>(w    + sbase + 4);
    const float4 va  = *reinterpret_cast<const float4*>(v2   + sbase);
    const float4 vb  = *reinterpret_cast<const float4*>(v2   + sbase + 4);
    const float4 ba  = *reinterpret_cast<const float4*>(bias + sbase);
    const float4 bb  = *reinterpret_cast<const float4*>(bias + sbase + 4);
    float wv[CHUNK] = {w0.x, w0.y, w0.z, w0.w, w1.x, w1.y, w1.z, w1.w};
    float vv[CHUNK] = {va.x, va.y, va.z, va.w, vb.x, vb.y, vb.z, vb.w};
    float bv[CHUNK] = {ba.x, ba.y, ba.z, ba.w, bb.x, bb.y, bb.z, bb.w};

    __shared__ float sA[2][NWARP];

    const int row0 = blockIdx.x * RPB;
    if (row0 >= rows) return;
    const int nr = (rows - row0 < RPB) ? (rows - row0) : RPB;

    const float* xt = x   + (long long)row0 * SEQ + sbase;
    float*       ot = out + (long long)row0 * SEQ + sbase;

    // prologue: load row 0, chain + scan
    float xc[CHUNK];
    {
        const float4 a0 = __ldcs(reinterpret_cast<const float4*>(xt));
        const float4 a1 = __ldcs(reinterpret_cast<const float4*>(xt + 4));
        xc[0]=a0.x; xc[1]=a0.y; xc[2]=a0.z; xc[3]=a0.w;
        xc[4]=a1.x; xc[5]=a1.y; xc[6]=a1.z; xc[7]=a1.w;
    }
    float S = chain_scan(xc, wv, d, m1, m2, m4, m8, m16, lane);

#pragma unroll 1
    for (int r = 0; r < nr - 1; r++) {
        const int p = r & 1;
        if (lane == 31) sA[p][warp] = S;

        // issue next row's loads before the barrier
        const float4 n0 = __ldcs(reinterpret_cast<const float4*>(xt + (long long)(r + 1) * SEQ));
        const float4 n1 = __ldcs(reinterpret_cast<const float4*>(xt + (long long)(r + 1) * SEQ + 4));

        __syncthreads();

        // stream (b): next row's chain + scan (registers/shuffles only)
        float xn[CHUNK] = {n0.x, n0.y, n0.z, n0.w, n1.x, n1.y, n1.z, n1.w};
        const float Sn = chain_scan(xn, wv, d, m1, m2, m4, m8, m16, lane);

        // stream (a): carry + epilogue + store for row r (independent of (b))
        float Cw = 0.f;
#pragma unroll
        for (int wi = 0; wi < NWARP; wi++)
            if (wi < warp) Cw = fmaf(d256, Cw, sA[p][wi]);
        float Ae = __shfl_up_sync(0xffffffffu, S, 1);
        if (lane == 0) Ae = 0.f;
        float C = fmaf(Me, Cw, Ae);

        float ov[CHUNK];
#pragma unroll
        for (int j = 0; j < CHUNK; j++) {
            ov[j] = fmaf(vv[j], xc[j], C + bv[j]);
            C = d * fmaf(xc[j], wv[j], C);
        }
        __stcs(reinterpret_cast<float4*>(ot + (long long)r * SEQ),
               make_float4(ov[0], ov[1], ov[2], ov[3]));
        __stcs(reinterpret_cast<float4*>(ot + (long long)r * SEQ + 4),
               make_float4(ov[4], ov[5], ov[6], ov[7]));

        // rotate pipeline
#pragma unroll
        for (int j = 0; j < CHUNK; j++) xc[j] = xn[j];
        S = Sn;
    }

    // final row (nr-1): no next row to overlap
    {
        const int r = nr - 1;
        const int p = r & 1;
        if (lane == 31) sA[p][warp] = S;
        __syncthreads();

        float Cw = 0.f;
#pragma unroll
        for (int wi = 0; wi < NWARP; wi++)
            if (wi < warp) Cw = fmaf(d256, Cw, sA[p][wi]);
        float Ae = __shfl_up_sync(0xffffffffu, S, 1);
        if (lane == 0) Ae = 0.f;
        float C = fmaf(Me, Cw, Ae);

        float ov[CHUNK];
#pragma unroll
        for (int j = 0; j < CHUNK; j++) {
            ov[j] = fmaf(vv[j], xc[j], C + bv[j]);
            C = d * fmaf(xc[j], wv[j], C);
        }
        __stcs(reinterpret_cast<float4*>(ot + (long long)r * SEQ),
               make_float4(ov[0], ov[1], ov[2], ov[3]));
        __stcs(reinterpret_cast<float4*>(ot + (long long)r * SEQ + 4),
               make_float4(ov[4], ov[5], ov[6], ov[7]));
    }
}

extern "C" void kernel_launch(void* const* d_in, const int* in_sizes, int n_in,
                              void* d_out, int out_size)
{
    const float* x     = (const float*)d_in[0];  // (B, E, S)
    const float* w     = (const float*)d_in[1];  // (1, S)
    const float* v2    = (const float*)d_in[2];  // (1, S)
    const float* bias  = (const float*)d_in[3];  // (S,)
    const float* decay = (const float*)d_in[4];  // (2, 1)
    float* out = (float*)d_out;

    const int rows   = in_sizes[0] / SEQ;        // B * E
    const int blocks = (rows + RPB - 1) / RPB;
    decay_scan_kernel<<<blocks, THREADS>>>(x, w, v2, bias, decay, out, rows);
}

// round 15
// speedup vs baseline: 1.1005x; 1.1005x over previous
#include <cuda_runtime.h>

// out[b,e,t] = v2[t]*x[b,e,t] + bias[t] + P[t]
// P[t] = sum_{s<t} x[b,e,s]*w[s]*d^(t-s),  d = clip(decay[1], 0.9, 1.0)
//
// Decayed prefix scan along S; all scan multipliers are data-independent
// powers of d. CHUNK=4 / 512 threads (high occupancy, proven issue=73%).
// Cross-warp combine done hierarchically: warp 0 shuffle-scans the 16 warp
// sums; every other thread pays only 1 LDS + 1 FMA (was 16 LDS + 16 FMA).

#define SEQ 2048
#define CHUNK 4
#define THREADS 512          // 512 * 4 = 2048 = SEQ
#define NWARP (THREADS / 32) // 16
#define RPB 8                // rows per block

__global__ void __launch_bounds__(THREADS, 3)
decay_scan_kernel(const float* __restrict__ x,
                  const float* __restrict__ w,
                  const float* __restrict__ v2,
                  const float* __restrict__ bias,
                  const float* __restrict__ decay,
                  float* __restrict__ out,
                  int rows)
{
    const int tid   = threadIdx.x;
    const int lane  = tid & 31;
    const int warp  = tid >> 5;
    const int sbase = tid * CHUNK;

    const float d = fminf(fmaxf(decay[1], 0.9f), 1.0f);

    // uniform decay powers
    const float d2 = d * d;
    const float d4 = d2 * d2;          // per-chunk multiplier
    const float m1  = d4;              // warp-scan steps
    const float m2  = m1 * m1;
    const float m4  = m2 * m2;
    const float m8  = m4 * m4;
    const float m16 = m8 * m8;
    const float d128 = m16 * m16;      // per-warp span
    const float c1 = d128;             // warp0 combine steps
    const float c2 = c1 * c1;
    const float c4 = c2 * c2;
    const float c8 = c4 * c4;
    const float Me = exp2f(4.0f * (float)lane * __log2f(d));  // d^(4*lane)

    // register-cached params for this thread's chunk
    const float4 wq = *reinterpret_cast<const float4*>(w    + sbase);
    const float4 vq = *reinterpret_cast<const float4*>(v2   + sbase);
    const float4 bq = *reinterpret_cast<const float4*>(bias + sbase);

    __shared__ float sA[2][NWARP];   // inclusive warp sums
    __shared__ float sC[2][NWARP];   // exclusive warp carries

    const int row0 = blockIdx.x * RPB;
    if (row0 >= rows) return;
    const int nr = (rows - row0 < RPB) ? (rows - row0) : RPB;

    const float* xt = x   + (long long)row0 * SEQ + sbase;
    float*       ot = out + (long long)row0 * SEQ + sbase;

    // prefetch first row
    float4 xa = __ldcs(reinterpret_cast<const float4*>(xt));

#pragma unroll 1
    for (int r = 0; r < nr; r++) {
        // prefetch next row (full iteration of distance)
        float4 xb;
        if (r + 1 < nr)
            xb = __ldcs(reinterpret_cast<const float4*>(xt + (long long)(r + 1) * SEQ));

        // per-chunk additive term: A = sum_j x[j]*w[j]*d^(CHUNK-j)
        float A;
        A = d * (xa.x * wq.x);
        A = d * fmaf(xa.y, wq.y, A);
        A = d * fmaf(xa.z, wq.z, A);
        A = d * fmaf(xa.w, wq.w, A);

        // warp Kogge-Stone scan (multipliers = powers of d)
        float Ai = A;
        {
            float ap;
            ap = __shfl_up_sync(0xffffffffu, Ai, 1);  if (lane >= 1)  Ai = fmaf(m1,  ap, Ai);
            ap = __shfl_up_sync(0xffffffffu, Ai, 2);  if (lane >= 2)  Ai = fmaf(m2,  ap, Ai);
            ap = __shfl_up_sync(0xffffffffu, Ai, 4);  if (lane >= 4)  Ai = fmaf(m4,  ap, Ai);
            ap = __shfl_up_sync(0xffffffffu, Ai, 8);  if (lane >= 8)  Ai = fmaf(m8,  ap, Ai);
            ap = __shfl_up_sync(0xffffffffu, Ai, 16); if (lane >= 16) Ai = fmaf(m16, ap, Ai);
        }

        const int p = r & 1;
        if (lane == 31) sA[p][warp] = Ai;
        __syncthreads();

        // warp 0: shuffle-scan the 16 warp sums -> exclusive carries
        if (warp == 0) {
            float v = (lane < NWARP) ? sA[p][lane] : 0.f;
            float t;
            t = __shfl_up_sync(0xffffffffu, v, 1);  if (lane >= 1) v = fmaf(c1, t, v);
            t = __shfl_up_sync(0xffffffffu, v, 2);  if (lane >= 2) v = fmaf(c2, t, v);
            t = __shfl_up_sync(0xffffffffu, v, 4);  if (lane >= 4) v = fmaf(c4, t, v);
            t = __shfl_up_sync(0xffffffffu, v, 8);  if (lane >= 8) v = fmaf(c8, t, v);
            float e = __shfl_up_sync(0xffffffffu, v, 1);
            if (lane == 0) e = 0.f;
            if (lane < NWARP) sC[p][lane] = e;
        }
        __syncthreads();

        // per-thread carry: 1 LDS + 2 FMA
        float Ae = __shfl_up_sync(0xffffffffu, Ai, 1);
        if (lane == 0) Ae = 0.f;
        float C = fmaf(Me, sC[p][warp], Ae);

        // epilogue: out[t] = v2[t]*x[t] + bias[t] + P[t]
        float4 o;
        o.x = fmaf(vq.x, xa.x, C + bq.x);  C = d * fmaf(xa.x, wq.x, C);
        o.y = fmaf(vq.y, xa.y, C + bq.y);  C = d * fmaf(xa.y, wq.y, C);
        o.z = fmaf(vq.z, xa.z, C + bq.z);  C = d * fmaf(xa.z, wq.z, C);
        o.w = fmaf(vq.w, xa.w, C + bq.w);

        __stcs(reinterpret_cast<float4*>(ot + (long long)r * SEQ), o);

        xa = xb;
    }
}

extern "C" void kernel_launch(void* const* d_in, const int* in_sizes, int n_in,
                              void* d_out, int out_size)
{
    const float* x     = (const float*)d_in[0];  // (B, E, S)
    const float* w     = (const float*)d_in[1];  // (1, S)
    const float* v2    = (const float*)d_in[2];  // (1, S)
    const float* bias  = (const float*)d_in[3];  // (S,)
    const float* decay = (const float*)d_in[4];  // (2, 1)
    float* out = (float*)d_out;

    const int rows   = in_sizes[0] / SEQ;        // B * E
    const int blocks = (rows + RPB - 1) / RPB;
    decay_scan_kernel<<<blocks, THREADS>>>(x, w, v2, bias, decay, out, rows);
}